// round 2
// baseline (speedup 1.0000x reference)
#include <cuda_runtime.h>
#include <math.h>

#define NQ   32768
#define NS   65536
#define KNN  30
#define TILE 512

// Scratch (static device globals — no allocation at launch time)
__device__ int   g_idx[NQ * KNN];
__device__ float g_h[NQ];

// ---------------------------------------------------------------------------
// Kernel 1: exact brute-force KNN, one thread per query.
// Sorted top-30 kept entirely in registers (fully unrolled), early-reject on
// the current 30th distance so the insertion path is rare (~19% of warp iters).
// ---------------------------------------------------------------------------
__global__ __launch_bounds__(128) void knn_kernel(const float* __restrict__ q,
                                                  const float* __restrict__ s) {
    __shared__ float4 tile[TILE];
    const int qi = blockIdx.x * 128 + threadIdx.x;

    const float qx = q[3 * qi + 0];
    const float qy = q[3 * qi + 1];
    const float qz = q[3 * qi + 2];
    const float q2 = qx * qx + qy * qy + qz * qz;

    float bd[KNN];
    int   bi[KNN];
#pragma unroll
    for (int i = 0; i < KNN; ++i) { bd[i] = 3.4e38f; bi[i] = 0; }

    float worst = 3.4e38f;

    for (int t0 = 0; t0 < NS; t0 += TILE) {
        __syncthreads();
        for (int j = threadIdx.x; j < TILE; j += 128) {
            const int sj = t0 + j;
            const float sx = s[3 * sj + 0];
            const float sy = s[3 * sj + 1];
            const float sz = s[3 * sj + 2];
            tile[j] = make_float4(sx, sy, sz, sx * sx + sy * sy + sz * sz);
        }
        __syncthreads();

#pragma unroll 4
        for (int j = 0; j < TILE; ++j) {
            const float4 v = tile[j];
            const float dot = fmaf(qx, v.x, fmaf(qy, v.y, qz * v.z));
            const float d2  = fmaf(-2.0f, dot, q2 + v.w);
            if (d2 < worst) {
                float dd = d2;
                int   ii = t0 + j;
#pragma unroll
                for (int i = 0; i < KNN; ++i) {
                    if (dd < bd[i]) {
                        const float tf = bd[i]; bd[i] = dd; dd = tf;
                        const int   ti = bi[i]; bi[i] = ii; ii = ti;
                    }
                }
                worst = bd[KNN - 1];
            }
        }
    }

    // bandwidth h = mean(sqrt(max(d2,0))) + 1e-8
    float hs = 0.0f;
#pragma unroll
    for (int i = 0; i < KNN; ++i) hs += sqrtf(fmaxf(bd[i], 0.0f));
    g_h[qi] = hs * (1.0f / (float)KNN) + 1e-8f;

#pragma unroll
    for (int i = 0; i < KNN; ++i) g_idx[qi * KNN + i] = bi[i];
}

// ---------------------------------------------------------------------------
// Kernel 2: RIMLS iterations, one warp per query (lane j = neighbor j, j<30).
// Exact replication of the reference's masked-update / done semantics.
// ---------------------------------------------------------------------------
__global__ __launch_bounds__(256) void rimls_kernel(const float* __restrict__ q,
                                                    const float* __restrict__ s,
                                                    const float* __restrict__ nrm,
                                                    float* __restrict__ out) {
    const int warp = (blockIdx.x * 256 + threadIdx.x) >> 5;
    const int lane = threadIdx.x & 31;
    if (warp >= NQ) return;

    const float qx = q[3 * warp + 0];
    const float qy = q[3 * warp + 1];
    const float qz = q[3 * warp + 2];
    const float h  = g_h[warp];
    const float inv_h2 = 1.0f / (h * h);

    const bool act = (lane < KNN);
    float nx = 0.f, ny = 0.f, nz = 0.f;
    float fx = 0.f, phi = 0.f;
    float gpx = 0.f, gpy = 0.f, gpz = 0.f;

    if (act) {
        const int id = g_idx[warp * KNN + lane];   // coalesced: lanes read consecutive
        const float sx = s[3 * id + 0];
        const float sy = s[3 * id + 1];
        const float sz = s[3 * id + 2];
        float ax = nrm[3 * id + 0];
        float ay = nrm[3 * id + 1];
        float az = nrm[3 * id + 2];
        // F.normalize(p=2, dim=1, eps=1e-8)
        const float nn  = sqrtf(ax * ax + ay * ay + az * az);
        const float inv = 1.0f / fmaxf(nn, 1e-8f);
        nx = ax * inv; ny = ay * inv; nz = az * inv;

        const float px = qx - sx, py = qy - sy, pz = qz - sz;
        fx = px * nx + py * ny + pz * nz;
        const float r2 = px * px + py * py + pz * pz;
        const float t  = fmaxf(1.0f - r2 * inv_h2, 0.0f);
        const float t2 = t * t;
        phi = t2 * t2;
        const float gc = -8.0f * inv_h2 * t * t2;
        gpx = gc * px; gpy = gc * py; gpz = gc * pz;
    }

    float f = 0.f, gx = 0.f, gy = 0.f, gz = 0.f;
    bool done = false;
    const float inv_sn2 = 1.0f / (0.8f * 0.8f);

    for (int it = 0; it < 3; ++it) {
        float alpha;
        if (it == 0) {
            alpha = 1.0f;
        } else {
            const float dx = nx - gx, dy = ny - gy, dz = nz - gz;
            alpha = expf(-(dx * dx + dy * dy + dz * dz) * inv_sn2);
        }
        const float w   = alpha * phi;           // 0 for inactive lanes (phi==0)
        const float gwx = alpha * gpx;
        const float gwy = alpha * gpy;
        const float gwz = alpha * gpz;

        float r0 = w;                            // sum w
        float r1 = w * fx;                       // sum w*fx
        float m0 = fmaf(gwx, fx, w * nx);        // sum(gw*fx) + sum(w*nn)
        float m1 = fmaf(gwy, fx, w * ny);
        float m2 = fmaf(gwz, fx, w * nz);
        float s0 = gwx, s1 = gwy, s2 = gwz;      // sum gw

#pragma unroll
        for (int off = 16; off; off >>= 1) {
            r0 += __shfl_xor_sync(0xffffffffu, r0, off);
            r1 += __shfl_xor_sync(0xffffffffu, r1, off);
            m0 += __shfl_xor_sync(0xffffffffu, m0, off);
            m1 += __shfl_xor_sync(0xffffffffu, m1, off);
            m2 += __shfl_xor_sync(0xffffffffu, m2, off);
            s0 += __shfl_xor_sync(0xffffffffu, s0, off);
            s1 += __shfl_xor_sync(0xffffffffu, s1, off);
            s2 += __shfl_xor_sync(0xffffffffu, s2, off);
        }

        const float sw    = r0 + 1e-8f;
        const float f_new = r1 / sw;
        const float gnx   = (m0 - f_new * s0) / sw;
        const float gny   = (m1 - f_new * s1) / sw;
        const float gnz   = (m2 - f_new * s2) / sw;

        const float delta = fabsf(f_new - f);
        if (!done) { f = f_new; gx = gnx; gy = gny; gz = gnz; }
        done = done || (delta < 1e-3f);          // MIN_IT = 1
    }

    if (lane == 0) {
        out[warp] = f;                           // potential [NQ]
        out[NQ + 3 * warp + 0] = gx;             // gradient [NQ,3]
        out[NQ + 3 * warp + 1] = gy;
        out[NQ + 3 * warp + 2] = gz;
    }
}

extern "C" void kernel_launch(void* const* d_in, const int* in_sizes, int n_in,
                              void* d_out, int out_size) {
    const float* q = (const float*)d_in[0];   // query_points   [32768,3]
    const float* s = (const float*)d_in[1];   // source_vertices[65536,3]
    const float* n = (const float*)d_in[2];   // source_normals [65536,3]
    float* out = (float*)d_out;               // [32768] potential + [32768,3] gradient

    knn_kernel<<<NQ / 128, 128>>>(q, s);
    rimls_kernel<<<NQ / 8, 256>>>(q, s, n, out);
}